// round 5
// baseline (speedup 1.0000x reference)
#include <cuda_runtime.h>
#include <cuda_bf16.h>
#include <cstdint>
#include <math.h>

#define K_CODES 2048
#define D_DIM   64
#define N_VEC   65536
#define M_TILE  256
#define NTILE   128
#define NT_CNT  (K_CODES / NTILE)     // 16
#define NTHREADS 512
#define NBLOCKS (N_VEC / M_TILE)      // 256

// ---- smem layout (bytes) ----
#define SM_X2    0                    // 256 f
#define SM_IDX   1024                 // 256 i
#define SM_ERR   2048                 // 256 f
#define SM_FLAGC 3072                 // 1 i
#define SM_FLAGS 3088                 // 256 i
#define SM_XROW  4112                 // 64 f
#define SM_A     4608                 // 2 splits x 32768 (frag order)
#define SPLIT_A  32768
#define SM_B     (SM_A + 2 * SPLIT_A) // 70144; 2 stages x 2 splits x 16384
#define SPLIT_B  16384
#define STAGE_B  (2 * SPLIT_B)
#define SMEM_TOTAL (SM_B + 2 * STAGE_B)   // 135680
// post-mainloop scratch overlays B region:
#define SM_RS    SM_B                 // 256*16 f
#define SM_RI    (SM_B + 16384)       // 256*16 i
#define SM_RS2   (SM_B + 32768)      // 256*16 f

__device__ __align__(256) uint2 g_cbF[2][32768];          // frag-order bf16 splits
__device__ __align__(256) float g_cbT[K_CODES * D_DIM];   // [k][d] fp32
__device__ float    g_cn2[K_CODES];
__device__ int      g_counts[K_CODES];
__device__ float    g_partial[NBLOCKS];
__device__ unsigned g_ticket;

// ---- helpers ----
__device__ __forceinline__ void mma16816(float* d, const uint32_t* a, const uint32_t* b) {
    asm volatile("mma.sync.aligned.m16n8k16.row.col.f32.bf16.bf16.f32 "
                 "{%0,%1,%2,%3}, {%4,%5,%6,%7}, {%8,%9}, {%0,%1,%2,%3};"
                 : "+f"(d[0]), "+f"(d[1]), "+f"(d[2]), "+f"(d[3])
                 : "r"(a[0]), "r"(a[1]), "r"(a[2]), "r"(a[3]), "r"(b[0]), "r"(b[1]));
}
#define CP_ASYNC16(dst, src) \
    asm volatile("cp.async.cg.shared.global [%0], [%1], 16;" :: "r"(dst), "l"(src) : "memory")
#define CP_COMMIT()  asm volatile("cp.async.commit_group;" ::: "memory")
#define CP_WAIT1()   asm volatile("cp.async.wait_group 1;" ::: "memory")
#define CP_WAIT0()   asm volatile("cp.async.wait_group 0;" ::: "memory")

__device__ __forceinline__ uint32_t smem_u32(const void* p) {
    uint32_t a;
    asm("{ .reg .u64 t; cvta.to.shared.u64 t, %1; cvt.u32.u64 %0, t; }" : "=r"(a) : "l"(p));
    return a;
}
__device__ __forceinline__ void split2(float v, uint16_t& s0, uint16_t& s1) {
    __nv_bfloat16 h0 = __float2bfloat16_rn(v);
    __nv_bfloat16 h1 = __float2bfloat16_rn(v - __bfloat162float(h0));
    s0 = __bfloat16_as_ushort(h0);
    s1 = __bfloat16_as_ushort(h1);
}

// ============================ prep kernels ============================
__global__ void vq_prep1(const float* __restrict__ cb) {
    int k = blockIdx.x * blockDim.x + threadIdx.x;
    if (k < K_CODES) {
        float s = 0.f;
        #pragma unroll 8
        for (int d = 0; d < D_DIM; d++) {
            float v = cb[(size_t)d * K_CODES + k];
            s = fmaf(v, v, s);
            g_cbT[(size_t)k * D_DIM + d] = v;
        }
        g_cn2[k] = s;
        g_counts[k] = 0;
    }
    if (k == 0) g_ticket = 0;
}

__global__ void vq_prep2(const float* __restrict__ cb) {
    int gid = blockIdx.x * blockDim.x + threadIdx.x;   // 32768 threads
    int lane = gid & 31, kb = (gid >> 5) & 3, g = (gid >> 7) & 15, tile = gid >> 11;
    int n  = tile * NTILE + g * 8 + (lane >> 2);
    int k0 = kb * 16 + (lane & 3) * 2;
    float v00 = cb[(size_t)(k0    ) * K_CODES + n];
    float v01 = cb[(size_t)(k0 + 1) * K_CODES + n];
    float v10 = cb[(size_t)(k0 + 8) * K_CODES + n];
    float v11 = cb[(size_t)(k0 + 9) * K_CODES + n];
    uint16_t a00, a01, b00, b01, c00, c01, d00, d01;
    split2(v00, a00, a01); split2(v01, b00, b01);
    split2(v10, c00, c01); split2(v11, d00, d01);
    int off = ((tile * 16 + g) * 4 + kb) * 32 + lane;
    g_cbF[0][off] = make_uint2((uint32_t)b00 << 16 | a00, (uint32_t)d00 << 16 | c00);
    g_cbF[1][off] = make_uint2((uint32_t)b01 << 16 | a01, (uint32_t)d01 << 16 | c01);
}

// ============================ main kernel ============================
__device__ __forceinline__ void load_b_tile(char* smc, int tile, int stage, int tid) {
    uint32_t base = smem_u32(smc + SM_B + stage * STAGE_B);
    #pragma unroll
    for (int it = 0; it < 4; it++) {                  // 2048 16B chunks / 512 thr
        int v = it * NTHREADS + tid;
        int sp = v >> 10;                             // split
        int c  = v & 1023;                            // chunk
        const char* src = (const char*)&g_cbF[sp][tile * 2048] + c * 16;
        CP_ASYNC16(base + sp * SPLIT_B + c * 16, src);
    }
}

__global__ __launch_bounds__(NTHREADS, 1) void vq_main(
    const float* __restrict__ x, float* __restrict__ out)
{
    extern __shared__ char smc[];
    const int tid = threadIdx.x;
    const int lane = tid & 31, warp = tid >> 5;
    const int mw = warp >> 2, nw = warp & 3;          // 4 M-warps x 4 N-warps
    const int qr = lane >> 2, qc = lane & 3;
    float* x2s   = (float*)(smc + SM_X2);
    int*   sidx  = (int*)(smc + SM_IDX);
    float* serr  = (float*)(smc + SM_ERR);
    int*   flagc = (int*)(smc + SM_FLAGC);
    int*   flags = (int*)(smc + SM_FLAGS);
    float* xrw   = (float*)(smc + SM_XROW);

    if (tid == 0) *flagc = 0;

    // ---- convert this CTA's 256-row x tile into 2 bf16 splits (frag order) ----
    {
        const int m = tid >> 1;
        const int dbase = (tid & 1) * 32;
        const float* xr = x + ((size_t)blockIdx.x * M_TILE + m) * D_DIM;
        float x2p = 0.f;
        #pragma unroll
        for (int jj = 0; jj < 8; jj++) {
            float4 v = __ldg((const float4*)xr + dbase / 4 + jj);
            float f[4] = { v.x, v.y, v.z, v.w };
            #pragma unroll
            for (int e = 0; e < 4; e++) {
                int d = dbase + jj * 4 + e;
                x2p = fmaf(f[e], f[e], x2p);
                uint16_t h0, h1;
                split2(f[e], h0, h1);
                int lane_f = ((m & 7) << 2) | ((d >> 1) & 3);
                int a_sel  = ((m >> 3) & 1) | (((d >> 3) & 1) << 1);
                int off = ((m >> 4) * 4 + (d >> 4)) * 512 + lane_f * 16 + a_sel * 4 + (d & 1) * 2;
                *(uint16_t*)(smc + SM_A + off) = h0;
                *(uint16_t*)(smc + SM_A + SPLIT_A + off) = h1;
            }
        }
        float x2f = x2p + __shfl_xor_sync(0xffffffffu, x2p, 1);
        if ((tid & 1) == 0) x2s[m] = x2f;
    }
    __syncthreads();

    // per-thread smem base addresses
    const char* Abase = smc + SM_A + lane * 16;
    const char* Bbase = smc + SM_B + lane * 8;

    const int pa[3] = { 1, 0, 0 };                    // small terms first
    const int pb[3] = { 0, 1, 0 };

    float b1[8], b2[8];
    int   i1[8];
    #pragma unroll
    for (int i = 0; i < 8; i++) { b1[i] = 3.4e38f; b2[i] = 3.4e38f; i1[i] = 0; }

    load_b_tile(smc, 0, 0, tid); CP_COMMIT();

    for (int t = 0; t < NT_CNT; t++) {
        const int st = t & 1;
        if (t + 1 < NT_CNT) { load_b_tile(smc, t + 1, 1 - st, tid); CP_COMMIT(); CP_WAIT1(); }
        else                { CP_WAIT0(); }
        __syncthreads();

        float acc[4][4][4];
        #pragma unroll
        for (int mt = 0; mt < 4; mt++)
            #pragma unroll
            for (int g = 0; g < 4; g++)
                #pragma unroll
                for (int e = 0; e < 4; e++) acc[mt][g][e] = 0.f;

        #pragma unroll
        for (int p = 0; p < 3; p++) {
            const char* Ab = Abase + pa[p] * SPLIT_A;
            const char* Bb = Bbase + st * STAGE_B + pb[p] * SPLIT_B;
            #pragma unroll
            for (int kb = 0; kb < 4; kb++) {
                uint2 bf[4];
                #pragma unroll
                for (int g = 0; g < 4; g++)
                    bf[g] = *(const uint2*)(Bb + ((nw * 4 + g) * 4 + kb) * 256);
                #pragma unroll
                for (int mt = 0; mt < 4; mt++) {
                    uint4 af = *(const uint4*)(Ab + ((mw * 4 + mt) * 4 + kb) * 512);
                    const uint32_t a[4] = { af.x, af.y, af.z, af.w };
                    #pragma unroll
                    for (int g = 0; g < 4; g++) {
                        const uint32_t b[2] = { bf[g].x, bf[g].y };
                        mma16816(acc[mt][g], a, b);
                    }
                }
            }
        }

        // ---- epilogue: scores + running (best, second-best) ----
        #pragma unroll
        for (int g = 0; g < 4; g++) {
            const int n0 = t * NTILE + nw * 32 + g * 8 + qc * 2;
            const float2 c2 = __ldg((const float2*)(g_cn2 + n0));
            #pragma unroll
            for (int mt = 0; mt < 4; mt++) {
                #pragma unroll
                for (int h = 0; h < 2; h++) {
                    const int sl = mt * 2 + h;
                    float s0 = fmaf(-2.f, acc[mt][g][h * 2 + 0], c2.x);
                    float s1 = fmaf(-2.f, acc[mt][g][h * 2 + 1], c2.y);
                    if (s0 < b1[sl]) { b2[sl] = b1[sl]; b1[sl] = s0; i1[sl] = n0; }
                    else if (s0 < b2[sl]) b2[sl] = s0;
                    if (s1 < b1[sl]) { b2[sl] = b1[sl]; b1[sl] = s1; i1[sl] = n0 + 1; }
                    else if (s1 < b2[sl]) b2[sl] = s1;
                }
            }
        }
        __syncthreads();
    }

    // ---- cross-thread merge: 16 contributors per row ----
    float* rs  = (float*)(smc + SM_RS);
    int*   ri  = (int*)(smc + SM_RI);
    float* rs2 = (float*)(smc + SM_RS2);
    const int cid = nw * 4 + qc;
    #pragma unroll
    for (int mt = 0; mt < 4; mt++)
        #pragma unroll
        for (int h = 0; h < 2; h++) {
            int m = mw * 64 + mt * 16 + qr + h * 8;
            rs[m * 16 + cid]  = b1[mt * 2 + h];
            ri[m * 16 + cid]  = i1[mt * 2 + h];
            rs2[m * 16 + cid] = b2[mt * 2 + h];
        }
    __syncthreads();

    if (tid < M_TILE) {
        float B1 = rs[tid * 16];  int I1 = ri[tid * 16];  float B2 = rs2[tid * 16];
        #pragma unroll
        for (int c = 1; c < 16; c++) {
            float b = rs[tid * 16 + c];
            int   i = ri[tid * 16 + c];
            float bb = rs2[tid * 16 + c];
            if (b < B1 || (b == B1 && i < I1)) { B2 = fminf(B1, bb); B1 = b; I1 = i; }
            else B2 = fminf(B2, b);
        }
        sidx[tid] = I1;
        serr[tid] = x2s[tid] + B1;
        float eps = 1e-4f * sqrtf(x2s[tid]) + 1e-5f;
        if (B2 - B1 < eps) {
            int fp = atomicAdd(flagc, 1);
            flags[fp] = tid;
        }
    }
    __syncthreads();

    // ---- exact fp32 re-check for flagged rows ----
    const int nf = *flagc;
    for (int f = 0; f < nf; f++) {
        const int r = flags[f];
        if (tid < 16)
            ((float4*)xrw)[tid] = __ldg((const float4*)(x + ((size_t)blockIdx.x * M_TILE + r) * D_DIM) + tid);
        __syncthreads();
        float lmin = 3.4e38f;
        int   lidx = 0;
        #pragma unroll
        for (int j = 0; j < 4; j++) {
            int k = tid * 4 + j;
            const float* cr = g_cbT + (size_t)k * D_DIM;
            float dot = 0.f;
            #pragma unroll 16
            for (int d = 0; d < D_DIM; d++) dot = fmaf(xrw[d], __ldg(cr + d), dot);
            float s = g_cn2[k] - 2.f * dot;
            if (s < lmin) { lmin = s; lidx = k; }
        }
        rs[tid] = lmin; ri[tid] = lidx;
        __syncthreads();
        for (int s = 256; s > 0; s >>= 1) {
            if (tid < s) {
                float o = rs[tid + s]; int oi = ri[tid + s];
                if (o < rs[tid] || (o == rs[tid] && oi < ri[tid])) { rs[tid] = o; ri[tid] = oi; }
            }
            __syncthreads();
        }
        if (tid == 0) { sidx[r] = ri[0]; serr[r] = x2s[r] + rs[0]; }
        __syncthreads();
    }

    // ---- histogram, gather, error reduction ----
    if (tid < M_TILE) atomicAdd(&g_counts[sidx[tid]], 1);
    __syncthreads();

    #pragma unroll
    for (int it = 0; it < 8; it++) {
        int idx4 = it * NTHREADS + tid;               // 4096 float4s
        int n = idx4 >> 4, d4 = idx4 & 15;
        float4 v = __ldg((const float4*)(g_cbT + (size_t)sidx[n] * D_DIM) + d4);
        ((float4*)(out + ((size_t)blockIdx.x * M_TILE + n) * D_DIM))[d4] = v;
    }

    rs[tid] = (tid < M_TILE) ? serr[tid] : 0.f;
    __syncthreads();
    for (int s = 256; s > 0; s >>= 1) {
        if (tid < s) rs[tid] += rs[tid + s];
        __syncthreads();
    }
    if (tid == 0) g_partial[blockIdx.x] = rs[0];

    // ---- last block: finalize scalars, reset for replay ----
    __shared__ int s_last;
    __threadfence();
    if (tid == 0) s_last = (atomicAdd(&g_ticket, 1u) == NBLOCKS - 1);
    __syncthreads();
    if (!s_last) return;
    __threadfence();

    rs[tid] = (tid < NBLOCKS) ? g_partial[tid] : 0.f;
    __syncthreads();
    for (int s = 256; s > 0; s >>= 1) {
        if (tid < s) rs[tid] += rs[tid + s];
        __syncthreads();
    }
    float mse = rs[0] / (float)((size_t)N_VEC * D_DIM);
    __syncthreads();

    const float invN = 1.f / (float)N_VEC;
    float e = 0.f;
    for (int j = tid; j < K_CODES; j += NTHREADS) {
        float pr = (float)g_counts[j] * invN;
        e += pr * logf(pr + 1e-10f);
    }
    rs[tid] = e;
    __syncthreads();
    for (int s = 256; s > 0; s >>= 1) {
        if (tid < s) rs[tid] += rs[tid + s];
        __syncthreads();
    }
    if (tid == 0) {
        out[(size_t)N_VEC * D_DIM + 0] = expf(-rs[0]);   // perplexity
        out[(size_t)N_VEC * D_DIM + 1] = mse;            // codebook_loss
        out[(size_t)N_VEC * D_DIM + 2] = 0.25f * mse;    // commitment_loss
    }
    __syncthreads();
    for (int j = tid; j < K_CODES; j += NTHREADS) g_counts[j] = 0;
    if (tid == 0) g_ticket = 0;
}

// ============================ launcher ============================
extern "C" void kernel_launch(void* const* d_in, const int* in_sizes, int n_in,
                              void* d_out, int out_size) {
    const float* a = (const float*)d_in[0];
    const float* b = (const float*)d_in[1];
    const float* x  = a;
    const float* cb = b;
    if (n_in >= 2 && in_sizes[0] < in_sizes[1]) { x = b; cb = a; }
    float* out = (float*)d_out;

    cudaFuncSetAttribute(vq_main, cudaFuncAttributeMaxDynamicSharedMemorySize, SMEM_TOTAL);

    vq_prep1<<<K_CODES / 256, 256>>>(cb);
    vq_prep2<<<128, 256>>>(cb);
    vq_main<<<NBLOCKS, NTHREADS, SMEM_TOTAL>>>(x, out);
}